// round 2
// baseline (speedup 1.0000x reference)
#include <cuda_runtime.h>
#include <cuda_bf16.h>

#define NTOK 16384
#define INF  512
#define HID  256
#define OUTF 16
#define NSTEPS 16
#define SIGMA2F 0.1f

// Scratch (device globals: sanctioned, no allocation)
__device__ __align__(16) __nv_bfloat16 g_Lbf[(size_t)NTOK * NTOK];       // 512 MB
__device__ __align__(16) float          g_U[2][NTOK * OUTF];             // u fp32, row-major
__device__ __align__(16) __nv_bfloat16  g_UbfT[2][OUTF * NTOK];          // u bf16, TRANSPOSED [col][row]

// ---------------------------------------------------------------------------
// Kernel 1: convert L fp32 -> bf16 (streaming)
// ---------------------------------------------------------------------------
__global__ void __launch_bounds__(256) convert_L(const float* __restrict__ L) {
    const size_t total = (size_t)NTOK * NTOK;
    const size_t stride = (size_t)gridDim.x * blockDim.x * 8;
    for (size_t i = ((size_t)blockIdx.x * blockDim.x + threadIdx.x) * 8; i < total; i += stride) {
        float4 x = __ldcs((const float4*)(L + i));
        float4 y = __ldcs((const float4*)(L + i + 4));
        __nv_bfloat162 p0 = __floats2bfloat162_rn(x.x, x.y);
        __nv_bfloat162 p1 = __floats2bfloat162_rn(x.z, x.w);
        __nv_bfloat162 p2 = __floats2bfloat162_rn(y.x, y.y);
        __nv_bfloat162 p3 = __floats2bfloat162_rn(y.z, y.w);
        uint4 o;
        o.x = *reinterpret_cast<unsigned*>(&p0);
        o.y = *reinterpret_cast<unsigned*>(&p1);
        o.z = *reinterpret_cast<unsigned*>(&p2);
        o.w = *reinterpret_cast<unsigned*>(&p3);
        *reinterpret_cast<uint4*>(&g_Lbf[i]) = o;
    }
}

// ---------------------------------------------------------------------------
// Kernel 2: u0 = (f @ Ws + bs) + (elu(f @ W1 + b1) @ W2 + b2)
// One block = 8 rows. Phase 1: 256 threads each own one hidden unit j,
// accumulate over k with f rows in smem. Phase 2: 128 threads own (row, col).
// ---------------------------------------------------------------------------
__global__ void __launch_bounds__(256) init_u0(
    const float* __restrict__ F,  const float* __restrict__ W1, const float* __restrict__ b1,
    const float* __restrict__ W2, const float* __restrict__ b2,
    const float* __restrict__ Ws, const float* __restrict__ bs)
{
    __shared__ float fs[8][INF];   // 16 KB
    __shared__ float hs[8][HID];   // 8 KB
    const int tid = threadIdx.x;
    const int rbase = blockIdx.x * 8;

    // load 8 feature rows (vectorized)
    {
        const float4* Fv = (const float4*)(F + (size_t)rbase * INF);
        float4* fsv = (float4*)&fs[0][0];
        #pragma unroll 4
        for (int i = tid; i < 8 * INF / 4; i += 256) fsv[i] = Fv[i];
    }
    __syncthreads();

    // hidden: h[rr][j] = elu(sum_k fs[rr][k]*W1[k][j] + b1[j])
    {
        const int j = tid;  // 0..255
        float acc[8];
        const float bb = b1[j];
        #pragma unroll
        for (int rr = 0; rr < 8; rr++) acc[rr] = bb;
        #pragma unroll 4
        for (int k = 0; k < INF; k++) {
            const float w = W1[k * HID + j];
            #pragma unroll
            for (int rr = 0; rr < 8; rr++) acc[rr] = fmaf(fs[rr][k], w, acc[rr]);
        }
        #pragma unroll
        for (int rr = 0; rr < 8; rr++) {
            const float x = acc[rr];
            hs[rr][j] = x > 0.0f ? x : expm1f(x);
        }
    }
    __syncthreads();

    // output: u0[rr][c]
    if (tid < 8 * OUTF) {
        const int rr = tid >> 4, c = tid & 15;
        float s0 = bs[c] + b2[c], s1 = 0.f, s2 = 0.f, s3 = 0.f;
        #pragma unroll 4
        for (int k = 0; k < INF; k += 4) {
            s0 = fmaf(fs[rr][k + 0], Ws[(k + 0) * OUTF + c], s0);
            s1 = fmaf(fs[rr][k + 1], Ws[(k + 1) * OUTF + c], s1);
            s2 = fmaf(fs[rr][k + 2], Ws[(k + 2) * OUTF + c], s2);
            s3 = fmaf(fs[rr][k + 3], Ws[(k + 3) * OUTF + c], s3);
        }
        #pragma unroll 4
        for (int j = 0; j < HID; j += 4) {
            s0 = fmaf(hs[rr][j + 0], W2[(j + 0) * OUTF + c], s0);
            s1 = fmaf(hs[rr][j + 1], W2[(j + 1) * OUTF + c], s1);
            s2 = fmaf(hs[rr][j + 2], W2[(j + 2) * OUTF + c], s2);
            s3 = fmaf(hs[rr][j + 3], W2[(j + 3) * OUTF + c], s3);
        }
        const float s = (s0 + s1) + (s2 + s3);
        const int r = rbase + rr;
        g_U[0][r * OUTF + c] = s;
        g_UbfT[0][c * NTOK + r] = __float2bfloat16(s);
    }
}

// ---------------------------------------------------------------------------
// Kernel 3: one diffusion step.  u_out = u_in - sigma2 * (L @ u_in)
// GEMM M=16384, N=16, K=16384 via mma.sync.m16n8k16 bf16 -> fp32.
// CTA: 256 threads (8 warps), each warp owns a 16x16 output tile. 128 CTAs.
// A fragments loaded straight from global (bf16 L), B from transposed u.
// ---------------------------------------------------------------------------
__device__ __forceinline__ void mma16816(float d[4], const unsigned a[4], const unsigned b[2]) {
    asm volatile(
        "mma.sync.aligned.m16n8k16.row.col.f32.bf16.bf16.f32 "
        "{%0,%1,%2,%3}, {%4,%5,%6,%7}, {%8,%9}, {%0,%1,%2,%3};\n"
        : "+f"(d[0]), "+f"(d[1]), "+f"(d[2]), "+f"(d[3])
        : "r"(a[0]), "r"(a[1]), "r"(a[2]), "r"(a[3]), "r"(b[0]), "r"(b[1]));
}

__global__ void __launch_bounds__(256) step_kernel(int inb, int outb, float* final_dst) {
    const int tid  = threadIdx.x;
    const int warp = tid >> 5;
    const int lane = tid & 31;
    const int g = lane >> 2;   // group 0..7
    const int t = lane & 3;    // thread-in-group

    const int rbase = blockIdx.x * 128 + warp * 16;
    const __nv_bfloat16* __restrict__ A0 = g_Lbf + (size_t)(rbase + g)     * NTOK;
    const __nv_bfloat16* __restrict__ A1 = g_Lbf + (size_t)(rbase + g + 8) * NTOK;
    const __nv_bfloat16* __restrict__ B0 = g_UbfT[inb] + (size_t)g       * NTOK;  // logical col g
    const __nv_bfloat16* __restrict__ B1 = g_UbfT[inb] + (size_t)(g + 8) * NTOK;  // logical col g+8

    float d0[4] = {0.f, 0.f, 0.f, 0.f};   // output cols 0..7
    float d1[4] = {0.f, 0.f, 0.f, 0.f};   // output cols 8..15

    const int t2 = 2 * t;

    for (int k0 = 0; k0 < NTOK; k0 += 64) {
        unsigned a[4][4], br0[4][2], br1[4][2];
        #pragma unroll
        for (int s = 0; s < 4; s++) {
            const int k = k0 + s * 16;
            // A fragment: a0=(g,klo) a1=(g+8,klo) a2=(g,khi) a3=(g+8,khi)
            a[s][0] = __ldcs((const unsigned*)(A0 + k + t2));
            a[s][1] = __ldcs((const unsigned*)(A1 + k + t2));
            a[s][2] = __ldcs((const unsigned*)(A0 + k + t2 + 8));
            a[s][3] = __ldcs((const unsigned*)(A1 + k + t2 + 8));
            // B fragment (col-major): b0 = {B[2t][n], B[2t+1][n]} contiguous in k
            br0[s][0] = *(const unsigned*)(B0 + k + t2);
            br0[s][1] = *(const unsigned*)(B0 + k + t2 + 8);
            br1[s][0] = *(const unsigned*)(B1 + k + t2);
            br1[s][1] = *(const unsigned*)(B1 + k + t2 + 8);
        }
        #pragma unroll
        for (int s = 0; s < 4; s++) {
            mma16816(d0, a[s], br0[s]);
            mma16816(d1, a[s], br1[s]);
        }
    }

    // epilogue: u_out = u_in - sigma2 * d ; write fp32 + transposed bf16
    const float* __restrict__ Ui = g_U[inb];
    float* __restrict__ Uo = g_U[outb];
    __nv_bfloat16* __restrict__ UT = g_UbfT[outb];
    const int r0 = rbase + g, r1 = r0 + 8;

    #pragma unroll
    for (int h = 0; h < 2; h++) {
        const float* dd = h ? d1 : d0;
        const int cc = t2 + 8 * h;
        const float v00 = Ui[r0 * OUTF + cc]     - SIGMA2F * dd[0];
        const float v01 = Ui[r0 * OUTF + cc + 1] - SIGMA2F * dd[1];
        const float v10 = Ui[r1 * OUTF + cc]     - SIGMA2F * dd[2];
        const float v11 = Ui[r1 * OUTF + cc + 1] - SIGMA2F * dd[3];
        *(float2*)(Uo + r0 * OUTF + cc) = make_float2(v00, v01);
        *(float2*)(Uo + r1 * OUTF + cc) = make_float2(v10, v11);
        UT[(cc    ) * NTOK + r0] = __float2bfloat16(v00);
        UT[(cc + 1) * NTOK + r0] = __float2bfloat16(v01);
        UT[(cc    ) * NTOK + r1] = __float2bfloat16(v10);
        UT[(cc + 1) * NTOK + r1] = __float2bfloat16(v11);
        if (final_dst) {
            *(float2*)(final_dst + r0 * OUTF + cc) = make_float2(v00, v01);
            *(float2*)(final_dst + r1 * OUTF + cc) = make_float2(v10, v11);
        }
    }
}

// ---------------------------------------------------------------------------
extern "C" void kernel_launch(void* const* d_in, const int* in_sizes, int n_in,
                              void* d_out, int out_size) {
    const float* F  = (const float*)d_in[0];
    const float* L  = (const float*)d_in[1];
    const float* W1 = (const float*)d_in[2];
    const float* b1 = (const float*)d_in[3];
    const float* W2 = (const float*)d_in[4];
    const float* b2 = (const float*)d_in[5];
    const float* Ws = (const float*)d_in[6];
    const float* bs = (const float*)d_in[7];

    convert_L<<<4096, 256>>>(L);
    init_u0<<<NTOK / 8, 256>>>(F, W1, b1, W2, b2, Ws, bs);
    for (int s = 0; s < NSTEPS; s++) {
        step_kernel<<<NTOK / 128, 256>>>(s & 1, (s + 1) & 1,
                                         s == NSTEPS - 1 ? (float*)d_out : nullptr);
    }
}

// round 5
// speedup vs baseline: 2.0877x; 2.0877x over previous
#include <cuda_runtime.h>
#include <cuda_bf16.h>

#define NTOK 16384
#define INF  512
#define HID  256
#define OUTF 16
#define NSTEPS 16
#define SIGMA2F 0.1f
#define KSPLITS 8
#define KSEG (NTOK / KSPLITS)   // 2048

// Scratch (device globals: sanctioned, no allocation)
__device__ __align__(16) __nv_bfloat16 g_Lbf[(size_t)NTOK * NTOK];       // 512 MB
__device__ __align__(16) float          g_U[2][NTOK * OUTF];             // u fp32, row-major
__device__ __align__(16) __nv_bfloat16  g_UbfT[2][OUTF * NTOK];          // u bf16, TRANSPOSED [col][row]
__device__ __align__(16) float          g_P[NTOK * OUTF];                // K-split partials (zero at steady state)

// ---------------------------------------------------------------------------
// Kernel 1: convert L fp32 -> bf16 (streaming)
// ---------------------------------------------------------------------------
__global__ void __launch_bounds__(256) convert_L(const float* __restrict__ L) {
    const size_t total = (size_t)NTOK * NTOK;
    const size_t stride = (size_t)gridDim.x * blockDim.x * 8;
    for (size_t i = ((size_t)blockIdx.x * blockDim.x + threadIdx.x) * 8; i < total; i += stride) {
        float4 x = __ldcs((const float4*)(L + i));
        float4 y = __ldcs((const float4*)(L + i + 4));
        __nv_bfloat162 p0 = __floats2bfloat162_rn(x.x, x.y);
        __nv_bfloat162 p1 = __floats2bfloat162_rn(x.z, x.w);
        __nv_bfloat162 p2 = __floats2bfloat162_rn(y.x, y.y);
        __nv_bfloat162 p3 = __floats2bfloat162_rn(y.z, y.w);
        uint4 o;
        o.x = *reinterpret_cast<unsigned*>(&p0);
        o.y = *reinterpret_cast<unsigned*>(&p1);
        o.z = *reinterpret_cast<unsigned*>(&p2);
        o.w = *reinterpret_cast<unsigned*>(&p3);
        *reinterpret_cast<uint4*>(&g_Lbf[i]) = o;
    }
}

// ---------------------------------------------------------------------------
// Kernel 2: u0 = (f @ Ws + bs) + (elu(f @ W1 + b1) @ W2 + b2)
// ---------------------------------------------------------------------------
__global__ void __launch_bounds__(256) init_u0(
    const float* __restrict__ F,  const float* __restrict__ W1, const float* __restrict__ b1,
    const float* __restrict__ W2, const float* __restrict__ b2,
    const float* __restrict__ Ws, const float* __restrict__ bs)
{
    __shared__ float fs[8][INF];   // 16 KB
    __shared__ float hs[8][HID];   // 8 KB
    const int tid = threadIdx.x;
    const int rbase = blockIdx.x * 8;

    {
        const float4* Fv = (const float4*)(F + (size_t)rbase * INF);
        float4* fsv = (float4*)&fs[0][0];
        #pragma unroll 4
        for (int i = tid; i < 8 * INF / 4; i += 256) fsv[i] = Fv[i];
    }
    __syncthreads();

    {
        const int j = tid;  // 0..255
        float acc[8];
        const float bb = b1[j];
        #pragma unroll
        for (int rr = 0; rr < 8; rr++) acc[rr] = bb;
        #pragma unroll 4
        for (int k = 0; k < INF; k++) {
            const float w = W1[k * HID + j];
            #pragma unroll
            for (int rr = 0; rr < 8; rr++) acc[rr] = fmaf(fs[rr][k], w, acc[rr]);
        }
        #pragma unroll
        for (int rr = 0; rr < 8; rr++) {
            const float x = acc[rr];
            hs[rr][j] = x > 0.0f ? x : expm1f(x);
        }
    }
    __syncthreads();

    if (tid < 8 * OUTF) {
        const int rr = tid >> 4, c = tid & 15;
        float s0 = bs[c] + b2[c], s1 = 0.f, s2 = 0.f, s3 = 0.f;
        #pragma unroll 4
        for (int k = 0; k < INF; k += 4) {
            s0 = fmaf(fs[rr][k + 0], Ws[(k + 0) * OUTF + c], s0);
            s1 = fmaf(fs[rr][k + 1], Ws[(k + 1) * OUTF + c], s1);
            s2 = fmaf(fs[rr][k + 2], Ws[(k + 2) * OUTF + c], s2);
            s3 = fmaf(fs[rr][k + 3], Ws[(k + 3) * OUTF + c], s3);
        }
        #pragma unroll 4
        for (int j = 0; j < HID; j += 4) {
            s0 = fmaf(hs[rr][j + 0], W2[(j + 0) * OUTF + c], s0);
            s1 = fmaf(hs[rr][j + 1], W2[(j + 1) * OUTF + c], s1);
            s2 = fmaf(hs[rr][j + 2], W2[(j + 2) * OUTF + c], s2);
            s3 = fmaf(hs[rr][j + 3], W2[(j + 3) * OUTF + c], s3);
        }
        const float s = (s0 + s1) + (s2 + s3);
        const int r = rbase + rr;
        g_U[0][r * OUTF + c] = s;
        g_UbfT[0][c * NTOK + r] = __float2bfloat16(s);
    }
}

// ---------------------------------------------------------------------------
// Kernel 3: partial GEMM for one diffusion step (K-split).
// grid = (128 row-tiles, KSPLITS). Warp = 16 rows x KSEG. Partials -> g_P via atomics.
// ---------------------------------------------------------------------------
__device__ __forceinline__ void mma16816(float d[4], const unsigned a[4], const unsigned b[2]) {
    asm volatile(
        "mma.sync.aligned.m16n8k16.row.col.f32.bf16.bf16.f32 "
        "{%0,%1,%2,%3}, {%4,%5,%6,%7}, {%8,%9}, {%0,%1,%2,%3};\n"
        : "+f"(d[0]), "+f"(d[1]), "+f"(d[2]), "+f"(d[3])
        : "r"(a[0]), "r"(a[1]), "r"(a[2]), "r"(a[3]), "r"(b[0]), "r"(b[1]));
}

__global__ void __launch_bounds__(256) step_partial(int inb) {
    const int tid  = threadIdx.x;
    const int warp = tid >> 5;
    const int lane = tid & 31;
    const int g = lane >> 2;   // group 0..7
    const int t = lane & 3;    // thread-in-group

    const int rbase = blockIdx.x * 128 + warp * 16;
    const int kbase = blockIdx.y * KSEG;
    const __nv_bfloat16* __restrict__ A0 = g_Lbf + (size_t)(rbase + g)     * NTOK + kbase;
    const __nv_bfloat16* __restrict__ A1 = g_Lbf + (size_t)(rbase + g + 8) * NTOK + kbase;
    const __nv_bfloat16* __restrict__ B0 = g_UbfT[inb] + (size_t)g       * NTOK + kbase;
    const __nv_bfloat16* __restrict__ B1 = g_UbfT[inb] + (size_t)(g + 8) * NTOK + kbase;

    float d0[4] = {0.f, 0.f, 0.f, 0.f};   // output cols 0..7
    float d1[4] = {0.f, 0.f, 0.f, 0.f};   // output cols 8..15

    const int t2 = 2 * t;

    for (int k0 = 0; k0 < KSEG; k0 += 64) {
        unsigned a[4][4], br0[4][2], br1[4][2];
        #pragma unroll
        for (int s = 0; s < 4; s++) {
            const int k = k0 + s * 16;
            a[s][0] = __ldcs((const unsigned*)(A0 + k + t2));
            a[s][1] = __ldcs((const unsigned*)(A1 + k + t2));
            a[s][2] = __ldcs((const unsigned*)(A0 + k + t2 + 8));
            a[s][3] = __ldcs((const unsigned*)(A1 + k + t2 + 8));
            br0[s][0] = *(const unsigned*)(B0 + k + t2);
            br0[s][1] = *(const unsigned*)(B0 + k + t2 + 8);
            br1[s][0] = *(const unsigned*)(B1 + k + t2);
            br1[s][1] = *(const unsigned*)(B1 + k + t2 + 8);
        }
        #pragma unroll
        for (int s = 0; s < 4; s++) {
            mma16816(d0, a[s], br0[s]);
            mma16816(d1, a[s], br1[s]);
        }
    }

    const int r0 = rbase + g, r1 = r0 + 8;
    #pragma unroll
    for (int h = 0; h < 2; h++) {
        const float* dd = h ? d1 : d0;
        const int cc = t2 + 8 * h;
        atomicAdd(&g_P[r0 * OUTF + cc],     dd[0]);
        atomicAdd(&g_P[r0 * OUTF + cc + 1], dd[1]);
        atomicAdd(&g_P[r1 * OUTF + cc],     dd[2]);
        atomicAdd(&g_P[r1 * OUTF + cc + 1], dd[3]);
    }
}

// ---------------------------------------------------------------------------
// Kernel 4: finalize step.  u_out = u_in - sigma2 * P; rezero P.
// One thread per row. Transposed bf16 stores coalesce across lanes.
// ---------------------------------------------------------------------------
__global__ void __launch_bounds__(256) step_finalize(int inb, int outb, float* final_dst) {
    const int r = blockIdx.x * 256 + threadIdx.x;
    const float* __restrict__ Ui = g_U[inb] + r * OUTF;
    float* __restrict__ Uo = g_U[outb] + r * OUTF;
    float* __restrict__ P  = g_P + r * OUTF;
    __nv_bfloat16* __restrict__ UT = g_UbfT[outb];

    float v[OUTF];
    #pragma unroll
    for (int i = 0; i < OUTF / 4; i++) {
        float4 u4 = *(const float4*)(Ui + 4 * i);
        float4 p4 = *(const float4*)(P + 4 * i);
        v[4*i+0] = u4.x - SIGMA2F * p4.x;
        v[4*i+1] = u4.y - SIGMA2F * p4.y;
        v[4*i+2] = u4.z - SIGMA2F * p4.z;
        v[4*i+3] = u4.w - SIGMA2F * p4.w;
        *(float4*)(Uo + 4 * i) = make_float4(v[4*i+0], v[4*i+1], v[4*i+2], v[4*i+3]);
        *(float4*)(P + 4 * i) = make_float4(0.f, 0.f, 0.f, 0.f);
        if (final_dst) *(float4*)(final_dst + r * OUTF + 4 * i)
            = make_float4(v[4*i+0], v[4*i+1], v[4*i+2], v[4*i+3]);
    }
    #pragma unroll
    for (int c = 0; c < OUTF; c++) UT[c * NTOK + r] = __float2bfloat16(v[c]);
}

// ---------------------------------------------------------------------------
extern "C" void kernel_launch(void* const* d_in, const int* in_sizes, int n_in,
                              void* d_out, int out_size) {
    const float* F  = (const float*)d_in[0];
    const float* L  = (const float*)d_in[1];
    const float* W1 = (const float*)d_in[2];
    const float* b1 = (const float*)d_in[3];
    const float* W2 = (const float*)d_in[4];
    const float* b2 = (const float*)d_in[5];
    const float* Ws = (const float*)d_in[6];
    const float* bs = (const float*)d_in[7];

    convert_L<<<4096, 256>>>(L);
    init_u0<<<NTOK / 8, 256>>>(F, W1, b1, W2, b2, Ws, bs);
    for (int s = 0; s < NSTEPS; s++) {
        dim3 grid(NTOK / 128, KSPLITS);
        step_partial<<<grid, 256>>>(s & 1);
        step_finalize<<<NTOK / 256, 256>>>(s & 1, (s + 1) & 1,
                                           s == NSTEPS - 1 ? (float*)d_out : nullptr);
    }
}

// round 6
// speedup vs baseline: 4.5391x; 2.1742x over previous
#include <cuda_runtime.h>
#include <cuda_bf16.h>

#define NTOK 16384
#define INF  512
#define HID  256
#define OUTF 16
#define NSTEPS 16
#define SIGMA2F 0.1f
#define KSPLITS 16
#define KSEG (NTOK / KSPLITS)          // 1024
#define KT_TOTAL (NTOK / 16)           // 1024 k-tiles
#define RT_TOTAL (NTOK / 16)           // 1024 row-tiles
#define SLICES_PER_CTA (KSEG / 16)     // 64

// Scratch (device globals: sanctioned, no allocation)
// g_Lbf: L in FRAGMENT-MAJOR layout: tile (rt,kt) -> 512B block at ((rt*1024+kt)*512),
//        lane l owns 16B: {(row g,k lo),(row g+8,k lo),(row g,k hi),(row g+8,k hi)} pairs.
__device__ __align__(16) __nv_bfloat16 g_Lbf[(size_t)NTOK * NTOK];       // 512 MB
__device__ __align__(16) float          g_U[2][NTOK * OUTF];             // u fp32, row-major
// g_Bfrag: u in B-fragment-major layout: slice s (16 k-rows) -> 512B, lane l -> uint4
__device__ __align__(16) __nv_bfloat16  g_Bfrag[2][OUTF * NTOK];         // 512 KB each
__device__ __align__(16) float          g_P[NTOK * OUTF];                // K-split partials (zero at steady state)

// ---------------------------------------------------------------------------
// Helper: write one fp32 value (row r, col c) into B-fragment layout as bf16
// ---------------------------------------------------------------------------
__device__ __forceinline__ void write_bfrag(__nv_bfloat16* Bf, int r, int c, float v) {
    const int s = r >> 4, p = r & 15;
    const int g = c & 7;
    const int tt = (p & 7) >> 1;
    const int word = (p >> 3) + 2 * (c >> 3);
    const int lane = g * 4 + tt;
    Bf[s * 256 + lane * 8 + word * 2 + (p & 1)] = __float2bfloat16(v);
}

// ---------------------------------------------------------------------------
// Kernel 1: convert L fp32 -> bf16 fragment-major. One warp per 16x16 tile.
// ---------------------------------------------------------------------------
__global__ void __launch_bounds__(256) convert_L(const float* __restrict__ L) {
    const int gw = (blockIdx.x * 256 + threadIdx.x) >> 5;   // tile index
    const int lane = threadIdx.x & 31;
    const int rt = gw >> 10;           // row-tile
    const int kt = gw & 1023;          // k-tile
    const int g = lane >> 2, t = lane & 3;

    const float* __restrict__ p0 = L + (size_t)(rt * 16 + g) * NTOK + kt * 16 + 2 * t;
    const float* __restrict__ p1 = p0 + (size_t)8 * NTOK;

    const float2 w0 = __ldcs((const float2*)p0);
    const float2 w1 = __ldcs((const float2*)p1);
    const float2 w2 = __ldcs((const float2*)(p0 + 8));
    const float2 w3 = __ldcs((const float2*)(p1 + 8));

    __nv_bfloat162 b0 = __floats2bfloat162_rn(w0.x, w0.y);
    __nv_bfloat162 b1 = __floats2bfloat162_rn(w1.x, w1.y);
    __nv_bfloat162 b2 = __floats2bfloat162_rn(w2.x, w2.y);
    __nv_bfloat162 b3 = __floats2bfloat162_rn(w3.x, w3.y);

    uint4 o;
    o.x = *reinterpret_cast<unsigned*>(&b0);
    o.y = *reinterpret_cast<unsigned*>(&b1);
    o.z = *reinterpret_cast<unsigned*>(&b2);
    o.w = *reinterpret_cast<unsigned*>(&b3);
    reinterpret_cast<uint4*>(g_Lbf)[(size_t)gw * 32 + lane] = o;
}

// ---------------------------------------------------------------------------
// Kernel 2: u0 = (f @ Ws + bs) + (elu(f @ W1 + b1) @ W2 + b2)
// ---------------------------------------------------------------------------
__global__ void __launch_bounds__(256) init_u0(
    const float* __restrict__ F,  const float* __restrict__ W1, const float* __restrict__ b1,
    const float* __restrict__ W2, const float* __restrict__ b2,
    const float* __restrict__ Ws, const float* __restrict__ bs)
{
    __shared__ float fs[8][INF];   // 16 KB
    __shared__ float hs[8][HID];   // 8 KB
    const int tid = threadIdx.x;
    const int rbase = blockIdx.x * 8;

    {
        const float4* Fv = (const float4*)(F + (size_t)rbase * INF);
        float4* fsv = (float4*)&fs[0][0];
        #pragma unroll 4
        for (int i = tid; i < 8 * INF / 4; i += 256) fsv[i] = Fv[i];
    }
    __syncthreads();

    {
        const int j = tid;  // 0..255
        float acc[8];
        const float bb = b1[j];
        #pragma unroll
        for (int rr = 0; rr < 8; rr++) acc[rr] = bb;
        #pragma unroll 4
        for (int k = 0; k < INF; k++) {
            const float w = W1[k * HID + j];
            #pragma unroll
            for (int rr = 0; rr < 8; rr++) acc[rr] = fmaf(fs[rr][k], w, acc[rr]);
        }
        #pragma unroll
        for (int rr = 0; rr < 8; rr++) {
            const float x = acc[rr];
            hs[rr][j] = x > 0.0f ? x : expm1f(x);
        }
    }
    __syncthreads();

    if (tid < 8 * OUTF) {
        const int rr = tid >> 4, c = tid & 15;
        float s0 = bs[c] + b2[c], s1 = 0.f, s2 = 0.f, s3 = 0.f;
        #pragma unroll 4
        for (int k = 0; k < INF; k += 4) {
            s0 = fmaf(fs[rr][k + 0], Ws[(k + 0) * OUTF + c], s0);
            s1 = fmaf(fs[rr][k + 1], Ws[(k + 1) * OUTF + c], s1);
            s2 = fmaf(fs[rr][k + 2], Ws[(k + 2) * OUTF + c], s2);
            s3 = fmaf(fs[rr][k + 3], Ws[(k + 3) * OUTF + c], s3);
        }
        #pragma unroll 4
        for (int j = 0; j < HID; j += 4) {
            s0 = fmaf(hs[rr][j + 0], W2[(j + 0) * OUTF + c], s0);
            s1 = fmaf(hs[rr][j + 1], W2[(j + 1) * OUTF + c], s1);
            s2 = fmaf(hs[rr][j + 2], W2[(j + 2) * OUTF + c], s2);
            s3 = fmaf(hs[rr][j + 3], W2[(j + 3) * OUTF + c], s3);
        }
        const float s = (s0 + s1) + (s2 + s3);
        const int r = rbase + rr;
        g_U[0][r * OUTF + c] = s;
        write_bfrag(g_Bfrag[0], r, c, s);
    }
}

// ---------------------------------------------------------------------------
// Kernel 3: partial GEMM (K-split). grid = (128, KSPLITS), 8 warps/CTA.
// Warp = one 16-row tile x KSEG. A via one LDG.128 per 16x16 tile (frag-major).
// B frags for the CTA's K-range staged in smem once.
// ---------------------------------------------------------------------------
__device__ __forceinline__ void mma16816(float d[4], const uint4 a, const unsigned b0, const unsigned b1) {
    asm volatile(
        "mma.sync.aligned.m16n8k16.row.col.f32.bf16.bf16.f32 "
        "{%0,%1,%2,%3}, {%4,%5,%6,%7}, {%8,%9}, {%0,%1,%2,%3};\n"
        : "+f"(d[0]), "+f"(d[1]), "+f"(d[2]), "+f"(d[3])
        : "r"(a.x), "r"(a.y), "r"(a.z), "r"(a.w), "r"(b0), "r"(b1));
}

__global__ void __launch_bounds__(256, 6) step_partial(int inb) {
    __shared__ uint4 sB[SLICES_PER_CTA * 32];   // 32 KB: B frags for this K-range

    const int tid  = threadIdx.x;
    const int warp = tid >> 5;
    const int lane = tid & 31;

    const int rt = blockIdx.x * 8 + warp;                 // row-tile 0..1023
    const int kt0 = blockIdx.y * SLICES_PER_CTA;          // first k-tile

    // stage B fragments (shared by all 8 warps)
    {
        const uint4* __restrict__ Bg = reinterpret_cast<const uint4*>(g_Bfrag[inb]) + kt0 * 32;
        #pragma unroll 2
        for (int i = tid; i < SLICES_PER_CTA * 32; i += 256) sB[i] = Bg[i];
    }
    __syncthreads();

    const uint4* __restrict__ Af =
        reinterpret_cast<const uint4*>(g_Lbf) + ((size_t)rt * KT_TOTAL + kt0) * 32 + lane;

    float d0[4] = {0.f, 0.f, 0.f, 0.f};
    float d1[4] = {0.f, 0.f, 0.f, 0.f};

    for (int c = 0; c < SLICES_PER_CTA; c += 4) {
        uint4 a0 = __ldcs(Af + (c + 0) * 32);
        uint4 a1 = __ldcs(Af + (c + 1) * 32);
        uint4 a2 = __ldcs(Af + (c + 2) * 32);
        uint4 a3 = __ldcs(Af + (c + 3) * 32);

        uint4 b;
        b = sB[(c + 0) * 32 + lane]; mma16816(d0, a0, b.x, b.y); mma16816(d1, a0, b.z, b.w);
        b = sB[(c + 1) * 32 + lane]; mma16816(d0, a1, b.x, b.y); mma16816(d1, a1, b.z, b.w);
        b = sB[(c + 2) * 32 + lane]; mma16816(d0, a2, b.x, b.y); mma16816(d1, a2, b.z, b.w);
        b = sB[(c + 3) * 32 + lane]; mma16816(d0, a3, b.x, b.y); mma16816(d1, a3, b.z, b.w);
    }

    const int g = lane >> 2, t2 = 2 * (lane & 3);
    const int r0 = rt * 16 + g, r1 = r0 + 8;
    #pragma unroll
    for (int h = 0; h < 2; h++) {
        const float* dd = h ? d1 : d0;
        const int cc = t2 + 8 * h;
        atomicAdd(&g_P[r0 * OUTF + cc],     dd[0]);
        atomicAdd(&g_P[r0 * OUTF + cc + 1], dd[1]);
        atomicAdd(&g_P[r1 * OUTF + cc],     dd[2]);
        atomicAdd(&g_P[r1 * OUTF + cc + 1], dd[3]);
    }
}

// ---------------------------------------------------------------------------
// Kernel 4: finalize step.  u_out = u_in - sigma2 * P; rezero P; emit B-frags.
// ---------------------------------------------------------------------------
__global__ void __launch_bounds__(256) step_finalize(int inb, int outb, float* final_dst) {
    const int r = blockIdx.x * 256 + threadIdx.x;
    const float* __restrict__ Ui = g_U[inb] + r * OUTF;
    float* __restrict__ Uo = g_U[outb] + r * OUTF;
    float* __restrict__ P  = g_P + r * OUTF;

    float v[OUTF];
    #pragma unroll
    for (int i = 0; i < OUTF / 4; i++) {
        float4 u4 = *(const float4*)(Ui + 4 * i);
        float4 p4 = *(const float4*)(P + 4 * i);
        v[4*i+0] = u4.x - SIGMA2F * p4.x;
        v[4*i+1] = u4.y - SIGMA2F * p4.y;
        v[4*i+2] = u4.z - SIGMA2F * p4.z;
        v[4*i+3] = u4.w - SIGMA2F * p4.w;
        *(float4*)(Uo + 4 * i) = make_float4(v[4*i+0], v[4*i+1], v[4*i+2], v[4*i+3]);
        *(float4*)(P + 4 * i) = make_float4(0.f, 0.f, 0.f, 0.f);
        if (final_dst) *(float4*)(final_dst + r * OUTF + 4 * i)
            = make_float4(v[4*i+0], v[4*i+1], v[4*i+2], v[4*i+3]);
    }
    __nv_bfloat16* __restrict__ Bf = g_Bfrag[outb];
    #pragma unroll
    for (int c = 0; c < OUTF; c++) write_bfrag(Bf, r, c, v[c]);
}

// ---------------------------------------------------------------------------
extern "C" void kernel_launch(void* const* d_in, const int* in_sizes, int n_in,
                              void* d_out, int out_size) {
    const float* F  = (const float*)d_in[0];
    const float* L  = (const float*)d_in[1];
    const float* W1 = (const float*)d_in[2];
    const float* b1 = (const float*)d_in[3];
    const float* W2 = (const float*)d_in[4];
    const float* b2 = (const float*)d_in[5];
    const float* Ws = (const float*)d_in[6];
    const float* bs = (const float*)d_in[7];

    convert_L<<<(RT_TOTAL * KT_TOTAL) / 8, 256>>>(L);   // 1 warp per 16x16 tile
    init_u0<<<NTOK / 8, 256>>>(F, W1, b1, W2, b2, Ws, bs);
    for (int s = 0; s < NSTEPS; s++) {
        dim3 grid(RT_TOTAL / 8, KSPLITS);
        step_partial<<<grid, 256>>>(s & 1);
        step_finalize<<<NTOK / 256, 256>>>(s & 1, (s + 1) & 1,
                                           s == NSTEPS - 1 ? (float*)d_out : nullptr);
    }
}